// round 16
// baseline (speedup 1.0000x reference)
#include <cuda_runtime.h>
#include <cuda_bf16.h>
#include <mma.h>
#include <math.h>

using namespace nvcuda;

// ---------------- problem constants ----------------
#define NB 2
#define NT 2048
#define NC 1024
#define NH 16
#define NKV 4
#define ND 64
#define NF 3584
#define NE 8
#define NTOK 4096
#define WINW 1024
#define HCAP 9216

// ---------------- scratch ----------------
__device__ float g_xn [NTOK*NC];
__device__ float g_qb [NTOK*NC];
__device__ float g_kb [NTOK*NKV*ND];
__device__ float g_vb [NTOK*NKV*ND];
__device__ float g_att[NTOK*NC];
__device__ float g_probs[NTOK*NE];
__device__ float g_h1 [HCAP*(size_t)NF];
__device__ int   g_elist[NE*NTOK];
__device__ float g_egate[NE*NTOK];
__device__ int   g_ecnt[NE];
__device__ int   g_eoffp[NE+1];

// ---------------- cp.async helpers ----------------
__device__ __forceinline__ void cp16(void* dst, const void* src, bool valid) {
    unsigned d = (unsigned)__cvta_generic_to_shared(dst);
    int sz = valid ? 16 : 0;
    asm volatile("cp.async.cg.shared.global [%0], [%1], 16, %2;\n" :: "r"(d), "l"(src), "r"(sz));
}
__device__ __forceinline__ void cp_commit() { asm volatile("cp.async.commit_group;\n" ::); }
template<int Np> __device__ __forceinline__ void cp_wait() {
    asm volatile("cp.async.wait_group %0;\n" :: "n"(Np));
}

// ---------------- shared GEMM smem (BK=16, 2-stage — best measured config) ----------------
struct GemmSmem {
    float As[2][128][20];
    float Bs[2][16][132];
    int   rows[128];
    float stage[4][16][20];
};

// ---------------- tf32 pipelined GEMM core ----------------
// 128 threads / 4 warps (2x2), warp tile 64x64, block tile 128x128, BK=16, 2-stage.
template<int GATHER, int SCATTER, int RESID>
__device__ __forceinline__ void gemm_core(
    const float* __restrict__ A, const float* __restrict__ B, float* __restrict__ C,
    int cnt, int N, int K, int m0, int n0,
    const float* __restrict__ R, const int* __restrict__ rowlist,
    const float* __restrict__ gscale, GemmSmem* sm)
{
    const int tid = threadIdx.x;
    const int warp = tid >> 5, lane = tid & 31;
    const int wm = warp >> 1, wn = warp & 1;

    if (GATHER) {
        if (tid < 128) {
            int m = m0 + tid;
            sm->rows[tid] = (m < cnt) ? rowlist[m] : -1;
        }
        __syncthreads();
    }

    wmma::fragment<wmma::accumulator, 16, 16, 8, float> acc[4][4];
#pragma unroll
    for (int i = 0; i < 4; i++)
#pragma unroll
        for (int j = 0; j < 4; j++) {
            if (RESID)
                wmma::load_matrix_sync(acc[i][j],
                    R + (size_t)(m0 + wm*64 + i*16)*N + n0 + wn*64 + j*16,
                    N, wmma::mem_row_major);
            else
                wmma::fill_fragment(acc[i][j], 0.0f);
        }

    auto loadA = [&](int k0, int buf) {
#pragma unroll
        for (int it = 0; it < 4; it++) {
            int idx = tid + it*128;
            int r = idx >> 2, c4 = (idx & 3) << 2;
            bool valid; long srow;
            if (GATHER)      { int t = sm->rows[r]; valid = (t >= 0); srow = valid ? t : 0; }
            else if (SCATTER){ valid = (m0 + r) < cnt; srow = valid ? (m0 + r) : 0; }
            else             { valid = true; srow = m0 + r; }
            cp16(&sm->As[buf][r][c4], &A[(size_t)srow*K + k0 + c4], valid);
        }
    };
    auto loadB = [&](int k0, int buf) {
#pragma unroll
        for (int it = 0; it < 4; it++) {
            int idx = tid + it*128;
            int r = idx >> 5, c4 = (idx & 31) << 2;
            cp16(&sm->Bs[buf][r][c4], &B[(size_t)(k0 + r)*N + n0 + c4], true);
        }
    };

    loadA(0, 0); loadB(0, 0); cp_commit();

    const int KT = K / 16;
    for (int kt = 0; kt < KT; kt++) {
        if (kt + 1 < KT) {
            loadA((kt+1)*16, (kt+1) & 1);
            loadB((kt+1)*16, (kt+1) & 1);
            cp_commit();
            cp_wait<1>();
        } else {
            cp_wait<0>();
        }
        __syncthreads();
        const int b = kt & 1;
#pragma unroll
        for (int kk = 0; kk < 2; kk++) {
            wmma::fragment<wmma::matrix_a, 16, 16, 8, wmma::precision::tf32, wmma::row_major> af[4];
            wmma::fragment<wmma::matrix_b, 16, 16, 8, wmma::precision::tf32, wmma::row_major> bf[4];
#pragma unroll
            for (int i = 0; i < 4; i++)
                wmma::load_matrix_sync(af[i], &sm->As[b][wm*64 + i*16][kk*8], 20);
#pragma unroll
            for (int j = 0; j < 4; j++)
                wmma::load_matrix_sync(bf[j], &sm->Bs[b][kk*8][wn*64 + j*16], 132);
#pragma unroll
            for (int i = 0; i < 4; i++)
#pragma unroll
                for (int j = 0; j < 4; j++)
                    wmma::mma_sync(acc[i][j], af[i], bf[j], acc[i][j]);
        }
        __syncthreads();
    }

    if (SCATTER) {
#pragma unroll
        for (int i = 0; i < 4; i++)
#pragma unroll
            for (int j = 0; j < 4; j++) {
                wmma::store_matrix_sync(&sm->stage[warp][0][0], acc[i][j], 20, wmma::mem_row_major);
                __syncwarp();
#pragma unroll
                for (int t = 0; t < 8; t++) {
                    int el = t*32 + lane;
                    int r = el >> 4, c = el & 15;
                    int ml = wm*64 + i*16 + r;
                    if (m0 + ml < cnt) {
                        int gr = rowlist[m0 + ml];
                        float gv = gscale ? gscale[m0 + ml] : 1.0f;
                        atomicAdd(&C[(size_t)gr*N + n0 + wn*64 + j*16 + c],
                                  gv * sm->stage[warp][r][c]);
                    }
                }
                __syncwarp();
            }
    } else {
#pragma unroll
        for (int i = 0; i < 4; i++)
#pragma unroll
            for (int j = 0; j < 4; j++)
                wmma::store_matrix_sync(
                    C + (size_t)(m0 + wm*64 + i*16)*N + n0 + wn*64 + j*16,
                    acc[i][j], N, wmma::mem_row_major);
    }
}

// ---------------- GEMM kernel wrappers (static smem) ----------------
__global__ __launch_bounds__(128, 2)
void qkv_gemm(const float* __restrict__ Xn, const float* __restrict__ qw,
              const float* __restrict__ kw, const float* __restrict__ vw)
{
    __shared__ GemmSmem sm;
    int nb = blockIdx.y;
    const float* B; float* C; int N, n0;
    if (nb < 8)       { B = qw; C = g_qb; N = 1024; n0 = nb*128; }
    else if (nb < 10) { B = kw; C = g_kb; N = 256;  n0 = (nb-8)*128; }
    else              { B = vw; C = g_vb; N = 256;  n0 = (nb-10)*128; }
    gemm_core<0,0,0>(Xn, B, C, NTOK, N, NC, blockIdx.x*128, n0, nullptr, nullptr, nullptr, &sm);
}

__global__ __launch_bounds__(128, 2)
void oproj_gemm(const float* __restrict__ A, const float* __restrict__ B,
                float* __restrict__ C, const float* __restrict__ R)
{
    __shared__ GemmSmem sm;
    gemm_core<0,0,1>(A, B, C, NTOK, NC, NC, blockIdx.x*128, blockIdx.y*128, R, nullptr, nullptr, &sm);
}

__global__ __launch_bounds__(128, 2)
void down_gemm(const float* __restrict__ W3, float* __restrict__ Out)
{
    __shared__ GemmSmem sm;
    int e = blockIdx.z;
    int cnt = g_ecnt[e];
    int m0 = blockIdx.x * 128;
    if (m0 >= cnt) return;
    const float* A = g_h1 + (size_t)g_eoffp[e]*NF;
    gemm_core<0,1,0>(A, W3 + (size_t)e*NF*NC, Out, cnt, NC, NF, m0, blockIdx.y*128,
                     nullptr, g_elist + e*NTOK, g_egate + e*NTOK, &sm);
}

// ---------------- fused gate GEMM: h1 = silu(X@W2) * (X@W1), gathered rows ----------------
struct GateSmem {
    float As [2][128][20];
    float B1s[2][16][72];
    float B2s[2][16][72];
    int   rows[128];
};

__global__ __launch_bounds__(128, 2)
void gatefused_gemm(const float* __restrict__ Xn, const float* __restrict__ W1g,
                    const float* __restrict__ W2g)
{
    __shared__ GateSmem sm;
    int e = blockIdx.z;
    int cnt = g_ecnt[e];
    int m0 = blockIdx.x * 128;
    if (m0 >= cnt) return;
    int n0 = blockIdx.y * 64;
    const float* B1 = W1g + (size_t)e*NC*NF;
    const float* B2 = W2g + (size_t)e*NC*NF;
    float* H = g_h1 + (size_t)g_eoffp[e]*NF;
    const int* rowlist = g_elist + e*NTOK;

    const int tid = threadIdx.x;
    const int warp = tid >> 5;
    const int wm = warp >> 1, wn = warp & 1;

    {
        int m = m0 + tid;
        sm.rows[tid] = (m < cnt) ? rowlist[m] : -1;
    }
    __syncthreads();

    wmma::fragment<wmma::accumulator, 16, 16, 8, float> acc1[4][2], acc2[4][2];
#pragma unroll
    for (int i = 0; i < 4; i++)
#pragma unroll
        for (int j = 0; j < 2; j++) {
            wmma::fill_fragment(acc1[i][j], 0.0f);
            wmma::fill_fragment(acc2[i][j], 0.0f);
        }

    auto loadA = [&](int k0, int buf) {
#pragma unroll
        for (int it = 0; it < 4; it++) {
            int idx = tid + it*128;
            int r = idx >> 2, c4 = (idx & 3) << 2;
            int t = sm.rows[r];
            bool valid = (t >= 0);
            long srow = valid ? t : 0;
            cp16(&sm.As[buf][r][c4], &Xn[(size_t)srow*NC + k0 + c4], valid);
        }
    };
    auto loadB = [&](int k0, int buf) {
#pragma unroll
        for (int it = 0; it < 2; it++) {
            int idx = tid + it*128;
            int r = idx >> 4, c4 = (idx & 15) << 2;
            cp16(&sm.B1s[buf][r][c4], &B1[(size_t)(k0 + r)*NF + n0 + c4], true);
            cp16(&sm.B2s[buf][r][c4], &B2[(size_t)(k0 + r)*NF + n0 + c4], true);
        }
    };

    loadA(0, 0); loadB(0, 0); cp_commit();

    const int KT = NC / 16;
    for (int kt = 0; kt < KT; kt++) {
        if (kt + 1 < KT) {
            loadA((kt+1)*16, (kt+1) & 1);
            loadB((kt+1)*16, (kt+1) & 1);
            cp_commit();
            cp_wait<1>();
        } else {
            cp_wait<0>();
        }
        __syncthreads();
        const int b = kt & 1;
#pragma unroll
        for (int kk = 0; kk < 2; kk++) {
            wmma::fragment<wmma::matrix_a, 16, 16, 8, wmma::precision::tf32, wmma::row_major> af[4];
            wmma::fragment<wmma::matrix_b, 16, 16, 8, wmma::precision::tf32, wmma::row_major> b1f[2], b2f[2];
#pragma unroll
            for (int i = 0; i < 4; i++)
                wmma::load_matrix_sync(af[i], &sm.As[b][wm*64 + i*16][kk*8], 20);
#pragma unroll
            for (int j = 0; j < 2; j++) {
                wmma::load_matrix_sync(b1f[j], &sm.B1s[b][kk*8][wn*32 + j*16], 72);
                wmma::load_matrix_sync(b2f[j], &sm.B2s[b][kk*8][wn*32 + j*16], 72);
            }
#pragma unroll
            for (int i = 0; i < 4; i++)
#pragma unroll
                for (int j = 0; j < 2; j++) {
                    wmma::mma_sync(acc1[i][j], af[i], b1f[j], acc1[i][j]);
                    wmma::mma_sync(acc2[i][j], af[i], b2f[j], acc2[i][j]);
                }
        }
        __syncthreads();
    }

#pragma unroll
    for (int i = 0; i < 4; i++)
#pragma unroll
        for (int j = 0; j < 2; j++) {
#pragma unroll
            for (int k = 0; k < acc1[i][j].num_elements; k++) {
                float z = acc2[i][j].x[k];
                acc1[i][j].x[k] *= z / (1.0f + __expf(-z));
            }
            wmma::store_matrix_sync(
                H + (size_t)(m0 + wm*64 + i*16)*NF + n0 + wn*32 + j*16,
                acc1[i][j], NF, wmma::mem_row_major);
        }
}

// ---------------- rmsnorm (warp-shuffle reduction, 1 barrier) ----------------
__global__ void rmsnorm_kernel(const float* __restrict__ X, const float* __restrict__ W,
                               float* __restrict__ Y)
{
    int row = blockIdx.x;
    int tid = threadIdx.x;
    const float4* xr = (const float4*)(X + (size_t)row*NC);
    float4 xv = xr[tid];
    float s = xv.x*xv.x + xv.y*xv.y + xv.z*xv.z + xv.w*xv.w;
#pragma unroll
    for (int o = 16; o; o >>= 1) s += __shfl_xor_sync(0xffffffffu, s, o);
    __shared__ float wsum[8];
    if ((tid & 31) == 0) wsum[tid >> 5] = s;
    __syncthreads();
    float tot = wsum[0] + wsum[1] + wsum[2] + wsum[3]
              + wsum[4] + wsum[5] + wsum[6] + wsum[7];
    float rstd = rsqrtf(tot * (1.0f/NC) + 1e-5f);
    float4 wv = ((const float4*)W)[tid];
    ((float4*)(Y + (size_t)row*NC))[tid] =
        make_float4(xv.x*rstd*wv.x, xv.y*rstd*wv.y, xv.z*rstd*wv.z, xv.w*rstd*wv.w);
}

// ---------------- RoPE (q and k in one launch) ----------------
#define ROPE_QTOT (NTOK*NH*32)
#define ROPE_KTOT (NTOK*NKV*32)
__global__ void rope_kernel(const float* __restrict__ cosp, const float* __restrict__ sinp)
{
    int gid = blockIdx.x*blockDim.x + threadIdx.x;
    float* buf; int heads;
    if (gid < ROPE_QTOT) { buf = g_qb; heads = NH; }
    else {
        gid -= ROPE_QTOT;
        if (gid >= ROPE_KTOT) return;
        buf = g_kb; heads = NKV;
    }
    int p   = gid & 31;
    int h   = (gid >> 5) % heads;
    int row = gid / (32*heads);
    int t   = row & (NT-1);
    float c = cosp[t*32 + p], s = sinp[t*32 + p];
    float* base = buf + (size_t)row*heads*ND + h*ND + p*2;
    float x1 = base[0], x2 = base[1];
    base[0] = x1*c - x2*s;
    base[1] = x1*s + x2*c;
}

// ---------------- tensor-core flash attention: 64-query tile, 256 threads,
// occupancy 1, Q fragments hoisted to registers ----------------
struct AttnSmem {
    float Qs[64][68];
    float Ks[64][68];
    float Vs[64][68];
    float Ss[64][68];
    float Pst[64][68];
};

__global__ __launch_bounds__(256, 1)
void attn_kernel()
{
    extern __shared__ char smraw[];
    AttnSmem* sm = (AttnSmem*)smraw;
    const int tid  = threadIdx.x;
    const int warp = tid >> 5;
    const int wm = warp >> 1, wn = warp & 1;
    const int q0 = blockIdx.x * 64;
    const int bh = blockIdx.y;
    const int b = bh >> 4, h = bh & 15;
    const int kv = h >> 2;

    for (int idx = tid; idx < 64*16; idx += 256) {
        int r = idx >> 4, c4 = (idx & 15) << 2;
        float4 qv = *(const float4*)&g_qb[((size_t)(b*NT + q0 + r))*NC + h*ND + c4];
        qv.x *= 0.125f; qv.y *= 0.125f; qv.z *= 0.125f; qv.w *= 0.125f;
        *(float4*)&sm->Qs[r][c4] = qv;
    }

    const int row = tid >> 2;
    const int c0  = (tid & 3) * 16;
    const int iabs = q0 + row;
    float Oacc[16];
#pragma unroll
    for (int c = 0; c < 16; c++) Oacc[c] = 0.f;
    float mrow = -1e30f, lrow = 0.f;

    int t0beg = q0 - 1024; if (t0beg < 0) t0beg = 0;
    __syncthreads();

    // hoist loop-invariant Q fragments into registers (8 per warp)
    wmma::fragment<wmma::matrix_a, 16, 16, 8, wmma::precision::tf32, wmma::row_major> afq[8];
#pragma unroll
    for (int kk = 0; kk < 8; kk++)
        wmma::load_matrix_sync(afq[kk], &sm->Qs[wm*16][kk*8], 68);

    for (int t0 = t0beg; t0 <= q0; t0 += 64) {
        for (int idx = tid; idx < 64*16; idx += 256) {
            int r = idx >> 4, c4 = (idx & 15) << 2;
            size_t off = ((size_t)(b*NT + t0 + r))*(NKV*ND) + kv*ND + c4;
            *(float4*)&sm->Ks[r][c4] = *(const float4*)&g_kb[off];
            *(float4*)&sm->Vs[r][c4] = *(const float4*)&g_vb[off];
        }
        __syncthreads();

        // S = Q @ K^T (Q fragments already in registers)
        {
            wmma::fragment<wmma::accumulator, 16, 16, 8, float> sacc[2];
#pragma unroll
            for (int j = 0; j < 2; j++) wmma::fill_fragment(sacc[j], 0.f);
#pragma unroll
            for (int kk = 0; kk < 8; kk++) {
#pragma unroll
                for (int j = 0; j < 2; j++) {
                    wmma::fragment<wmma::matrix_b, 16, 16, 8, wmma::precision::tf32, wmma::col_major> bf;
                    wmma::load_matrix_sync(bf, &sm->Ks[wn*32 + j*16][kk*8], 68);
                    wmma::mma_sync(sacc[j], afq[kk], bf, sacc[j]);
                }
            }
#pragma unroll
            for (int j = 0; j < 2; j++)
                wmma::store_matrix_sync(&sm->Ss[wm*16][wn*32 + j*16], sacc[j], 68, wmma::mem_row_major);
        }
        __syncthreads();

        // streaming softmax: 4 threads/row, 16 cols each
        {
            int jlo = iabs - (WINW-1), jhi = iabs;
            float sv[16];
            float tmax = -1e30f;
#pragma unroll
            for (int c = 0; c < 16; c++) {
                int j = t0 + c0 + c;
                bool v = (j <= jhi) && (j >= jlo);
                float s = sm->Ss[row][c0 + c];
                sv[c] = v ? s : -1e30f;
                if (v) tmax = fmaxf(tmax, s);
            }
            tmax = fmaxf(tmax, __shfl_xor_sync(0xffffffffu, tmax, 1));
            tmax = fmaxf(tmax, __shfl_xor_sync(0xffffffffu, tmax, 2));
            float mnew = fmaxf(mrow, tmax);
            float alpha = __expf(mrow - mnew);
            float psum = 0.f;
#pragma unroll
            for (int c = 0; c < 16; c++) {
                float p = (sv[c] > -1e29f) ? __expf(sv[c] - mnew) : 0.f;
                sv[c] = p;
                psum += p;
            }
            psum += __shfl_xor_sync(0xffffffffu, psum, 1);
            psum += __shfl_xor_sync(0xffffffffu, psum, 2);
            lrow = lrow*alpha + psum;
            mrow = mnew;
#pragma unroll
            for (int c = 0; c < 16; c++) Oacc[c] *= alpha;
#pragma unroll
            for (int c = 0; c < 16; c++) sm->Ss[row][c0 + c] = sv[c];
        }
        __syncthreads();

        // Pst = P @ V
        {
            wmma::fragment<wmma::accumulator, 16, 16, 8, float> oacc[2];
#pragma unroll
            for (int j = 0; j < 2; j++) wmma::fill_fragment(oacc[j], 0.f);
#pragma unroll
            for (int kk = 0; kk < 8; kk++) {
                wmma::fragment<wmma::matrix_a, 16, 16, 8, wmma::precision::tf32, wmma::row_major> af;
                wmma::load_matrix_sync(af, &sm->Ss[wm*16][kk*8], 68);
#pragma unroll
                for (int j = 0; j < 2; j++) {
                    wmma::fragment<wmma::matrix_b, 16, 16, 8, wmma::precision::tf32, wmma::row_major> bf;
                    wmma::load_matrix_sync(bf, &sm->Vs[kk*8][wn*32 + j*16], 68);
                    wmma::mma_sync(oacc[j], af, bf, oacc[j]);
                }
            }
#pragma unroll
            for (int j = 0; j < 2; j++)
                wmma::store_matrix_sync(&sm->Pst[wm*16][wn*32 + j*16], oacc[j], 68, wmma::mem_row_major);
        }
        __syncthreads();

#pragma unroll
        for (int c = 0; c < 16; c++) Oacc[c] += sm->Pst[row][c0 + c];
    }

    float inv = 1.f / lrow;
    float* op = g_att + ((size_t)(b*NT + iabs))*NC + h*ND + c0;
#pragma unroll
    for (int c = 0; c < 16; c += 4) {
        *(float4*)&op[c] = make_float4(Oacc[c]*inv, Oacc[c+1]*inv, Oacc[c+2]*inv, Oacc[c+3]*inv);
    }
}

// ---------------- router (zeroes expert counters inline, block 0) ----------------
__global__ void router_logits_kernel(const float* __restrict__ Xn, const float* __restrict__ RW)
{
    if (blockIdx.x == 0 && threadIdx.x < NE) g_ecnt[threadIdx.x] = 0;
    int tok  = blockIdx.x*4 + (threadIdx.x >> 5);
    int lane = threadIdx.x & 31;
    float acc[NE];
#pragma unroll
    for (int e = 0; e < NE; e++) acc[e] = 0.f;
    const float* xr = Xn + (size_t)tok*NC;
    for (int d = lane; d < NC; d += 32) {
        float xv = xr[d];
        const float* rw = RW + (size_t)d*NE;
#pragma unroll
        for (int e = 0; e < NE; e++) acc[e] += xv * rw[e];
    }
#pragma unroll
    for (int off = 16; off; off >>= 1)
#pragma unroll
        for (int e = 0; e < NE; e++) acc[e] += __shfl_down_sync(0xffffffffu, acc[e], off);
    if (lane == 0) {
#pragma unroll
        for (int e = 0; e < NE; e++) g_probs[(size_t)tok*NE + e] = acc[e];
    }
}

__global__ void router_post_kernel()
{
    int tok = blockIdx.x*blockDim.x + threadIdx.x;
    if (tok >= NTOK) return;
    float l[NE];
#pragma unroll
    for (int e = 0; e < NE; e++) l[e] = g_probs[(size_t)tok*NE + e];
    float mx = l[0];
#pragma unroll
    for (int e = 1; e < NE; e++) mx = fmaxf(mx, l[e]);
    float sum = 0.f;
#pragma unroll
    for (int e = 0; e < NE; e++) { l[e] = __expf(l[e]-mx); sum += l[e]; }
    float inv = 1.f/sum;
#pragma unroll
    for (int e = 0; e < NE; e++) { l[e] *= inv; g_probs[(size_t)tok*NE + e] = l[e]; }
    int b1 = 0; float p1 = l[0];
#pragma unroll
    for (int e = 1; e < NE; e++) if (l[e] > p1) { p1 = l[e]; b1 = e; }
    int b2 = -1; float p2 = -1.f;
#pragma unroll
    for (int e = 0; e < NE; e++) if (e != b1 && l[e] > p2) { p2 = l[e]; b2 = e; }
    if (b2 < 0) { b2 = (b1 + 1) & 7; p2 = l[b2]; }
    float s2 = p1 + p2;
    int pos1 = atomicAdd(&g_ecnt[b1], 1);
    g_elist[b1*NTOK + pos1] = tok; g_egate[b1*NTOK + pos1] = p1/s2;
    int pos2 = atomicAdd(&g_ecnt[b2], 1);
    g_elist[b2*NTOK + pos2] = tok; g_egate[b2*NTOK + pos2] = p2/s2;
}

__global__ void eoffp_kernel()
{
    if (threadIdx.x == 0) {
        int off = 0;
#pragma unroll
        for (int e = 0; e < NE; e++) {
            g_eoffp[e] = off;
            off += ((g_ecnt[e] + 127) / 128) * 128;
        }
        g_eoffp[NE] = off;
    }
}

// ---------------- aux loss (prob-sum reduction fused in; one block, 8 warps) ----------------
__global__ void aux_kernel(float* __restrict__ out, int out_size)
{
    if (out_size < NTOK*NC + 1) return;
    int tid = threadIdx.x, w = tid >> 5, lane = tid & 31;
    float s = 0.f;
    for (int t = lane; t < NTOK; t += 32) s += g_probs[(size_t)t*NE + w];
#pragma unroll
    for (int o = 16; o; o >>= 1) s += __shfl_xor_sync(0xffffffffu, s, o);
    __shared__ float ps[NE];
    if (lane == 0) ps[w] = s;
    __syncthreads();
    if (tid == 0) {
        float a = 0.f;
#pragma unroll
        for (int e = 0; e < NE; e++) {
            float f = (float)g_ecnt[e] / (float)(NTOK*2);
            a += f * (ps[e] / (float)NTOK);
        }
        out[(size_t)NTOK*NC] = (float)NE * a;
    }
}

// ---------------- launch ----------------
extern "C" void kernel_launch(void* const* d_in, const int* in_sizes, int n_in,
                              void* d_out, int out_size)
{
    const float* x    = (const float*)d_in[0];
    const float* cosp = (const float*)d_in[1];
    const float* sinp = (const float*)d_in[2];
    const float* ln1  = (const float*)d_in[3];
    const float* q_w  = (const float*)d_in[4];
    const float* k_w  = (const float*)d_in[5];
    const float* v_w  = (const float*)d_in[6];
    const float* o_w  = (const float*)d_in[7];
    const float* ln2  = (const float*)d_in[8];
    const float* rw   = (const float*)d_in[9];
    const float* W1   = (const float*)d_in[10];
    const float* W2   = (const float*)d_in[11];
    const float* W3   = (const float*)d_in[12];
    float* out = (float*)d_out;

    float *xn, *att;
    cudaGetSymbolAddress((void**)&xn,  g_xn);
    cudaGetSymbolAddress((void**)&att, g_att);

    const int ATT_SMSZ = (int)sizeof(AttnSmem);
    cudaFuncSetAttribute(attn_kernel, cudaFuncAttributeMaxDynamicSharedMemorySize, ATT_SMSZ);

    // 1) pre-attention norm
    rmsnorm_kernel<<<NTOK, 256>>>(x, ln1, xn);
    // 2) fused QKV projections
    qkv_gemm<<<dim3(NTOK/128, 12), 128>>>(xn, q_w, k_w, v_w);
    // 3) RoPE (q + k in one launch)
    rope_kernel<<<(ROPE_QTOT + ROPE_KTOT + 255)/256, 256>>>(cosp, sinp);
    // 4) tensor-core flash attention (Q fragments register-resident)
    attn_kernel<<<dim3(NT/64, NB*NH), 256, ATT_SMSZ>>>();
    // 5) o-proj + residual
    oproj_gemm<<<dim3(NTOK/128, NC/128), 128>>>(att, o_w, out, x);
    // 6) pre-MoE norm
    rmsnorm_kernel<<<NTOK, 256>>>(out, ln2, xn);
    // 7) router
    router_logits_kernel<<<NTOK/4, 128>>>(xn, rw);
    router_post_kernel<<<NTOK/256, 256>>>();
    eoffp_kernel<<<1, 32>>>();
    // 8) experts — fused gate (W1+W2+silu), then gated down-proj scatter
    gatefused_gemm<<<dim3(NTOK/128, NF/64, NE), 128>>>(xn, W1, W2);
    down_gemm<<<dim3(NTOK/128, NC/128, NE), 128>>>(W3, out);
    // 9) aux loss (psum fused)
    aux_kernel<<<1, 256>>>(out, out_size);
}

// round 17
// speedup vs baseline: 1.0165x; 1.0165x over previous
#include <cuda_runtime.h>
#include <cuda_bf16.h>
#include <mma.h>
#include <math.h>

using namespace nvcuda;

// ---------------- problem constants ----------------
#define NB 2
#define NT 2048
#define NC 1024
#define NH 16
#define NKV 4
#define ND 64
#define NF 3584
#define NE 8
#define NTOK 4096
#define WINW 1024
#define HCAP 9216

// ---------------- scratch ----------------
__device__ float g_xn [NTOK*NC];
__device__ float g_qb [NTOK*NC];
__device__ float g_kb [NTOK*NKV*ND];
__device__ float g_vb [NTOK*NKV*ND];
__device__ float g_att[NTOK*NC];
__device__ float g_probs[NTOK*NE];
__device__ float g_h1 [HCAP*(size_t)NF];
__device__ int   g_elist[NE*NTOK];
__device__ float g_egate[NE*NTOK];
__device__ int   g_ecnt[NE];
__device__ int   g_eoffp[NE+1];

// ---------------- cp.async helpers ----------------
__device__ __forceinline__ void cp16(void* dst, const void* src, bool valid) {
    unsigned d = (unsigned)__cvta_generic_to_shared(dst);
    int sz = valid ? 16 : 0;
    asm volatile("cp.async.cg.shared.global [%0], [%1], 16, %2;\n" :: "r"(d), "l"(src), "r"(sz));
}
__device__ __forceinline__ void cp_commit() { asm volatile("cp.async.commit_group;\n" ::); }
template<int Np> __device__ __forceinline__ void cp_wait() {
    asm volatile("cp.async.wait_group %0;\n" :: "n"(Np));
}

// ---------------- shared GEMM smem (BK=16, 2-stage — best measured config) ----------------
struct GemmSmem {
    float As[2][128][20];
    float Bs[2][16][132];
    int   rows[128];
    float stage[4][16][20];
};

// ---------------- tf32 pipelined GEMM core ----------------
// 128 threads / 4 warps (2x2), warp tile 64x64, block tile 128x128, BK=16, 2-stage.
template<int GATHER, int SCATTER, int RESID>
__device__ __forceinline__ void gemm_core(
    const float* __restrict__ A, const float* __restrict__ B, float* __restrict__ C,
    int cnt, int N, int K, int m0, int n0,
    const float* __restrict__ R, const int* __restrict__ rowlist,
    const float* __restrict__ gscale, GemmSmem* sm)
{
    const int tid = threadIdx.x;
    const int warp = tid >> 5, lane = tid & 31;
    const int wm = warp >> 1, wn = warp & 1;

    if (GATHER) {
        if (tid < 128) {
            int m = m0 + tid;
            sm->rows[tid] = (m < cnt) ? rowlist[m] : -1;
        }
        __syncthreads();
    }

    wmma::fragment<wmma::accumulator, 16, 16, 8, float> acc[4][4];
#pragma unroll
    for (int i = 0; i < 4; i++)
#pragma unroll
        for (int j = 0; j < 4; j++) {
            if (RESID)
                wmma::load_matrix_sync(acc[i][j],
                    R + (size_t)(m0 + wm*64 + i*16)*N + n0 + wn*64 + j*16,
                    N, wmma::mem_row_major);
            else
                wmma::fill_fragment(acc[i][j], 0.0f);
        }

    auto loadA = [&](int k0, int buf) {
#pragma unroll
        for (int it = 0; it < 4; it++) {
            int idx = tid + it*128;
            int r = idx >> 2, c4 = (idx & 3) << 2;
            bool valid; long srow;
            if (GATHER)      { int t = sm->rows[r]; valid = (t >= 0); srow = valid ? t : 0; }
            else if (SCATTER){ valid = (m0 + r) < cnt; srow = valid ? (m0 + r) : 0; }
            else             { valid = true; srow = m0 + r; }
            cp16(&sm->As[buf][r][c4], &A[(size_t)srow*K + k0 + c4], valid);
        }
    };
    auto loadB = [&](int k0, int buf) {
#pragma unroll
        for (int it = 0; it < 4; it++) {
            int idx = tid + it*128;
            int r = idx >> 5, c4 = (idx & 31) << 2;
            cp16(&sm->Bs[buf][r][c4], &B[(size_t)(k0 + r)*N + n0 + c4], true);
        }
    };

    loadA(0, 0); loadB(0, 0); cp_commit();

    const int KT = K / 16;
    for (int kt = 0; kt < KT; kt++) {
        if (kt + 1 < KT) {
            loadA((kt+1)*16, (kt+1) & 1);
            loadB((kt+1)*16, (kt+1) & 1);
            cp_commit();
            cp_wait<1>();
        } else {
            cp_wait<0>();
        }
        __syncthreads();
        const int b = kt & 1;
#pragma unroll
        for (int kk = 0; kk < 2; kk++) {
            wmma::fragment<wmma::matrix_a, 16, 16, 8, wmma::precision::tf32, wmma::row_major> af[4];
            wmma::fragment<wmma::matrix_b, 16, 16, 8, wmma::precision::tf32, wmma::row_major> bf[4];
#pragma unroll
            for (int i = 0; i < 4; i++)
                wmma::load_matrix_sync(af[i], &sm->As[b][wm*64 + i*16][kk*8], 20);
#pragma unroll
            for (int j = 0; j < 4; j++)
                wmma::load_matrix_sync(bf[j], &sm->Bs[b][kk*8][wn*64 + j*16], 132);
#pragma unroll
            for (int i = 0; i < 4; i++)
#pragma unroll
                for (int j = 0; j < 4; j++)
                    wmma::mma_sync(acc[i][j], af[i], bf[j], acc[i][j]);
        }
        __syncthreads();
    }

    if (SCATTER) {
#pragma unroll
        for (int i = 0; i < 4; i++)
#pragma unroll
            for (int j = 0; j < 4; j++) {
                wmma::store_matrix_sync(&sm->stage[warp][0][0], acc[i][j], 20, wmma::mem_row_major);
                __syncwarp();
#pragma unroll
                for (int t = 0; t < 8; t++) {
                    int el = t*32 + lane;
                    int r = el >> 4, c = el & 15;
                    int ml = wm*64 + i*16 + r;
                    if (m0 + ml < cnt) {
                        int gr = rowlist[m0 + ml];
                        float gv = gscale ? gscale[m0 + ml] : 1.0f;
                        atomicAdd(&C[(size_t)gr*N + n0 + wn*64 + j*16 + c],
                                  gv * sm->stage[warp][r][c]);
                    }
                }
                __syncwarp();
            }
    } else {
#pragma unroll
        for (int i = 0; i < 4; i++)
#pragma unroll
            for (int j = 0; j < 4; j++)
                wmma::store_matrix_sync(
                    C + (size_t)(m0 + wm*64 + i*16)*N + n0 + wn*64 + j*16,
                    acc[i][j], N, wmma::mem_row_major);
    }
}

// ---------------- GEMM kernel wrappers (static smem) ----------------
__global__ __launch_bounds__(128, 2)
void qkv_gemm(const float* __restrict__ Xn, const float* __restrict__ qw,
              const float* __restrict__ kw, const float* __restrict__ vw)
{
    __shared__ GemmSmem sm;
    int nb = blockIdx.y;
    const float* B; float* C; int N, n0;
    if (nb < 8)       { B = qw; C = g_qb; N = 1024; n0 = nb*128; }
    else if (nb < 10) { B = kw; C = g_kb; N = 256;  n0 = (nb-8)*128; }
    else              { B = vw; C = g_vb; N = 256;  n0 = (nb-10)*128; }
    gemm_core<0,0,0>(Xn, B, C, NTOK, N, NC, blockIdx.x*128, n0, nullptr, nullptr, nullptr, &sm);
}

__global__ __launch_bounds__(128, 2)
void oproj_gemm(const float* __restrict__ A, const float* __restrict__ B,
                float* __restrict__ C, const float* __restrict__ R)
{
    __shared__ GemmSmem sm;
    gemm_core<0,0,1>(A, B, C, NTOK, NC, NC, blockIdx.x*128, blockIdx.y*128, R, nullptr, nullptr, &sm);
}

__global__ __launch_bounds__(128, 2)
void down_gemm(const float* __restrict__ W3, float* __restrict__ Out)
{
    __shared__ GemmSmem sm;
    int e = blockIdx.z;
    int cnt = g_ecnt[e];
    int m0 = blockIdx.x * 128;
    if (m0 >= cnt) return;
    const float* A = g_h1 + (size_t)g_eoffp[e]*NF;
    gemm_core<0,1,0>(A, W3 + (size_t)e*NF*NC, Out, cnt, NC, NF, m0, blockIdx.y*128,
                     nullptr, g_elist + e*NTOK, g_egate + e*NTOK, &sm);
}

// ---------------- fused gate GEMM: h1 = silu(X@W2) * (X@W1), gathered rows ----------------
struct GateSmem {
    float As [2][128][20];
    float B1s[2][16][72];
    float B2s[2][16][72];
    int   rows[128];
};

__global__ __launch_bounds__(128, 2)
void gatefused_gemm(const float* __restrict__ Xn, const float* __restrict__ W1g,
                    const float* __restrict__ W2g)
{
    __shared__ GateSmem sm;
    int e = blockIdx.z;
    int cnt = g_ecnt[e];
    int m0 = blockIdx.x * 128;
    if (m0 >= cnt) return;
    int n0 = blockIdx.y * 64;
    const float* B1 = W1g + (size_t)e*NC*NF;
    const float* B2 = W2g + (size_t)e*NC*NF;
    float* H = g_h1 + (size_t)g_eoffp[e]*NF;
    const int* rowlist = g_elist + e*NTOK;

    const int tid = threadIdx.x;
    const int warp = tid >> 5;
    const int wm = warp >> 1, wn = warp & 1;

    {
        int m = m0 + tid;
        sm.rows[tid] = (m < cnt) ? rowlist[m] : -1;
    }
    __syncthreads();

    wmma::fragment<wmma::accumulator, 16, 16, 8, float> acc1[4][2], acc2[4][2];
#pragma unroll
    for (int i = 0; i < 4; i++)
#pragma unroll
        for (int j = 0; j < 2; j++) {
            wmma::fill_fragment(acc1[i][j], 0.0f);
            wmma::fill_fragment(acc2[i][j], 0.0f);
        }

    auto loadA = [&](int k0, int buf) {
#pragma unroll
        for (int it = 0; it < 4; it++) {
            int idx = tid + it*128;
            int r = idx >> 2, c4 = (idx & 3) << 2;
            int t = sm.rows[r];
            bool valid = (t >= 0);
            long srow = valid ? t : 0;
            cp16(&sm.As[buf][r][c4], &Xn[(size_t)srow*NC + k0 + c4], valid);
        }
    };
    auto loadB = [&](int k0, int buf) {
#pragma unroll
        for (int it = 0; it < 2; it++) {
            int idx = tid + it*128;
            int r = idx >> 4, c4 = (idx & 15) << 2;
            cp16(&sm.B1s[buf][r][c4], &B1[(size_t)(k0 + r)*NF + n0 + c4], true);
            cp16(&sm.B2s[buf][r][c4], &B2[(size_t)(k0 + r)*NF + n0 + c4], true);
        }
    };

    loadA(0, 0); loadB(0, 0); cp_commit();

    const int KT = NC / 16;
    for (int kt = 0; kt < KT; kt++) {
        if (kt + 1 < KT) {
            loadA((kt+1)*16, (kt+1) & 1);
            loadB((kt+1)*16, (kt+1) & 1);
            cp_commit();
            cp_wait<1>();
        } else {
            cp_wait<0>();
        }
        __syncthreads();
        const int b = kt & 1;
#pragma unroll
        for (int kk = 0; kk < 2; kk++) {
            wmma::fragment<wmma::matrix_a, 16, 16, 8, wmma::precision::tf32, wmma::row_major> af[4];
            wmma::fragment<wmma::matrix_b, 16, 16, 8, wmma::precision::tf32, wmma::row_major> b1f[2], b2f[2];
#pragma unroll
            for (int i = 0; i < 4; i++)
                wmma::load_matrix_sync(af[i], &sm.As[b][wm*64 + i*16][kk*8], 20);
#pragma unroll
            for (int j = 0; j < 2; j++) {
                wmma::load_matrix_sync(b1f[j], &sm.B1s[b][kk*8][wn*32 + j*16], 72);
                wmma::load_matrix_sync(b2f[j], &sm.B2s[b][kk*8][wn*32 + j*16], 72);
            }
#pragma unroll
            for (int i = 0; i < 4; i++)
#pragma unroll
                for (int j = 0; j < 2; j++) {
                    wmma::mma_sync(acc1[i][j], af[i], b1f[j], acc1[i][j]);
                    wmma::mma_sync(acc2[i][j], af[i], b2f[j], acc2[i][j]);
                }
        }
        __syncthreads();
    }

#pragma unroll
    for (int i = 0; i < 4; i++)
#pragma unroll
        for (int j = 0; j < 2; j++) {
#pragma unroll
            for (int k = 0; k < acc1[i][j].num_elements; k++) {
                float z = acc2[i][j].x[k];
                acc1[i][j].x[k] *= z / (1.0f + __expf(-z));
            }
            wmma::store_matrix_sync(
                H + (size_t)(m0 + wm*64 + i*16)*NF + n0 + wn*32 + j*16,
                acc1[i][j], NF, wmma::mem_row_major);
        }
}

// ---------------- rmsnorm (warp-shuffle reduction, 1 barrier) ----------------
__global__ void rmsnorm_kernel(const float* __restrict__ X, const float* __restrict__ W,
                               float* __restrict__ Y)
{
    int row = blockIdx.x;
    int tid = threadIdx.x;
    const float4* xr = (const float4*)(X + (size_t)row*NC);
    float4 xv = xr[tid];
    float s = xv.x*xv.x + xv.y*xv.y + xv.z*xv.z + xv.w*xv.w;
#pragma unroll
    for (int o = 16; o; o >>= 1) s += __shfl_xor_sync(0xffffffffu, s, o);
    __shared__ float wsum[8];
    if ((tid & 31) == 0) wsum[tid >> 5] = s;
    __syncthreads();
    float tot = wsum[0] + wsum[1] + wsum[2] + wsum[3]
              + wsum[4] + wsum[5] + wsum[6] + wsum[7];
    float rstd = rsqrtf(tot * (1.0f/NC) + 1e-5f);
    float4 wv = ((const float4*)W)[tid];
    ((float4*)(Y + (size_t)row*NC))[tid] =
        make_float4(xv.x*rstd*wv.x, xv.y*rstd*wv.y, xv.z*rstd*wv.z, xv.w*rstd*wv.w);
}

// ---------------- RoPE (q and k in one launch) ----------------
#define ROPE_QTOT (NTOK*NH*32)
#define ROPE_KTOT (NTOK*NKV*32)
__global__ void rope_kernel(const float* __restrict__ cosp, const float* __restrict__ sinp)
{
    int gid = blockIdx.x*blockDim.x + threadIdx.x;
    float* buf; int heads;
    if (gid < ROPE_QTOT) { buf = g_qb; heads = NH; }
    else {
        gid -= ROPE_QTOT;
        if (gid >= ROPE_KTOT) return;
        buf = g_kb; heads = NKV;
    }
    int p   = gid & 31;
    int h   = (gid >> 5) % heads;
    int row = gid / (32*heads);
    int t   = row & (NT-1);
    float c = cosp[t*32 + p], s = sinp[t*32 + p];
    float* base = buf + (size_t)row*heads*ND + h*ND + p*2;
    float x1 = base[0], x2 = base[1];
    base[0] = x1*c - x2*s;
    base[1] = x1*s + x2*c;
}

// ---------------- tensor-core flash attention: 64-query tile, 256 threads, occ 2
// (best measured configuration; Q fragments re-loaded from smem each tile) ----------------
struct AttnSmem {
    float Qs[64][68];
    float Ks[64][68];
    float Vs[64][68];
    float Ss[64][68];
    float Pst[64][68];
};

__global__ __launch_bounds__(256, 2)
void attn_kernel()
{
    extern __shared__ char smraw[];
    AttnSmem* sm = (AttnSmem*)smraw;
    const int tid  = threadIdx.x;
    const int warp = tid >> 5;
    const int wm = warp >> 1, wn = warp & 1;
    const int q0 = blockIdx.x * 64;
    const int bh = blockIdx.y;
    const int b = bh >> 4, h = bh & 15;
    const int kv = h >> 2;

    for (int idx = tid; idx < 64*16; idx += 256) {
        int r = idx >> 4, c4 = (idx & 15) << 2;
        float4 qv = *(const float4*)&g_qb[((size_t)(b*NT + q0 + r))*NC + h*ND + c4];
        qv.x *= 0.125f; qv.y *= 0.125f; qv.z *= 0.125f; qv.w *= 0.125f;
        *(float4*)&sm->Qs[r][c4] = qv;
    }

    const int row = tid >> 2;
    const int c0  = (tid & 3) * 16;
    const int iabs = q0 + row;
    float Oacc[16];
#pragma unroll
    for (int c = 0; c < 16; c++) Oacc[c] = 0.f;
    float mrow = -1e30f, lrow = 0.f;

    int t0beg = q0 - 1024; if (t0beg < 0) t0beg = 0;
    __syncthreads();

    for (int t0 = t0beg; t0 <= q0; t0 += 64) {
        for (int idx = tid; idx < 64*16; idx += 256) {
            int r = idx >> 4, c4 = (idx & 15) << 2;
            size_t off = ((size_t)(b*NT + t0 + r))*(NKV*ND) + kv*ND + c4;
            *(float4*)&sm->Ks[r][c4] = *(const float4*)&g_kb[off];
            *(float4*)&sm->Vs[r][c4] = *(const float4*)&g_vb[off];
        }
        __syncthreads();

        {
            wmma::fragment<wmma::accumulator, 16, 16, 8, float> sacc[2];
#pragma unroll
            for (int j = 0; j < 2; j++) wmma::fill_fragment(sacc[j], 0.f);
#pragma unroll
            for (int kk = 0; kk < 8; kk++) {
                wmma::fragment<wmma::matrix_a, 16, 16, 8, wmma::precision::tf32, wmma::row_major> af;
                wmma::load_matrix_sync(af, &sm->Qs[wm*16][kk*8], 68);
#pragma unroll
                for (int j = 0; j < 2; j++) {
                    wmma::fragment<wmma::matrix_b, 16, 16, 8, wmma::precision::tf32, wmma::col_major> bf;
                    wmma::load_matrix_sync(bf, &sm->Ks[wn*32 + j*16][kk*8], 68);
                    wmma::mma_sync(sacc[j], af, bf, sacc[j]);
                }
            }
#pragma unroll
            for (int j = 0; j < 2; j++)
                wmma::store_matrix_sync(&sm->Ss[wm*16][wn*32 + j*16], sacc[j], 68, wmma::mem_row_major);
        }
        __syncthreads();

        {
            int jlo = iabs - (WINW-1), jhi = iabs;
            float sv[16];
            float tmax = -1e30f;
#pragma unroll
            for (int c = 0; c < 16; c++) {
                int j = t0 + c0 + c;
                bool v = (j <= jhi) && (j >= jlo);
                float s = sm->Ss[row][c0 + c];
                sv[c] = v ? s : -1e30f;
                if (v) tmax = fmaxf(tmax, s);
            }
            tmax = fmaxf(tmax, __shfl_xor_sync(0xffffffffu, tmax, 1));
            tmax = fmaxf(tmax, __shfl_xor_sync(0xffffffffu, tmax, 2));
            float mnew = fmaxf(mrow, tmax);
            float alpha = __expf(mrow - mnew);
            float psum = 0.f;
#pragma unroll
            for (int c = 0; c < 16; c++) {
                float p = (sv[c] > -1e29f) ? __expf(sv[c] - mnew) : 0.f;
                sv[c] = p;
                psum += p;
            }
            psum += __shfl_xor_sync(0xffffffffu, psum, 1);
            psum += __shfl_xor_sync(0xffffffffu, psum, 2);
            lrow = lrow*alpha + psum;
            mrow = mnew;
#pragma unroll
            for (int c = 0; c < 16; c++) Oacc[c] *= alpha;
#pragma unroll
            for (int c = 0; c < 16; c++) sm->Ss[row][c0 + c] = sv[c];
        }
        __syncthreads();

        {
            wmma::fragment<wmma::accumulator, 16, 16, 8, float> oacc[2];
#pragma unroll
            for (int j = 0; j < 2; j++) wmma::fill_fragment(oacc[j], 0.f);
#pragma unroll
            for (int kk = 0; kk < 8; kk++) {
                wmma::fragment<wmma::matrix_a, 16, 16, 8, wmma::precision::tf32, wmma::row_major> af;
                wmma::load_matrix_sync(af, &sm->Ss[wm*16][kk*8], 68);
#pragma unroll
                for (int j = 0; j < 2; j++) {
                    wmma::fragment<wmma::matrix_b, 16, 16, 8, wmma::precision::tf32, wmma::row_major> bf;
                    wmma::load_matrix_sync(bf, &sm->Vs[kk*8][wn*32 + j*16], 68);
                    wmma::mma_sync(oacc[j], af, bf, oacc[j]);
                }
            }
#pragma unroll
            for (int j = 0; j < 2; j++)
                wmma::store_matrix_sync(&sm->Pst[wm*16][wn*32 + j*16], oacc[j], 68, wmma::mem_row_major);
        }
        __syncthreads();

#pragma unroll
        for (int c = 0; c < 16; c++) Oacc[c] += sm->Pst[row][c0 + c];
    }

    float inv = 1.f / lrow;
    float* op = g_att + ((size_t)(b*NT + iabs))*NC + h*ND + c0;
#pragma unroll
    for (int c = 0; c < 16; c += 4) {
        *(float4*)&op[c] = make_float4(Oacc[c]*inv, Oacc[c+1]*inv, Oacc[c+2]*inv, Oacc[c+3]*inv);
    }
}

// ---------------- router (zeroes expert counters inline, block 0) ----------------
__global__ void router_logits_kernel(const float* __restrict__ Xn, const float* __restrict__ RW)
{
    if (blockIdx.x == 0 && threadIdx.x < NE) g_ecnt[threadIdx.x] = 0;
    int tok  = blockIdx.x*4 + (threadIdx.x >> 5);
    int lane = threadIdx.x & 31;
    float acc[NE];
#pragma unroll
    for (int e = 0; e < NE; e++) acc[e] = 0.f;
    const float* xr = Xn + (size_t)tok*NC;
    for (int d = lane; d < NC; d += 32) {
        float xv = xr[d];
        const float* rw = RW + (size_t)d*NE;
#pragma unroll
        for (int e = 0; e < NE; e++) acc[e] += xv * rw[e];
    }
#pragma unroll
    for (int off = 16; off; off >>= 1)
#pragma unroll
        for (int e = 0; e < NE; e++) acc[e] += __shfl_down_sync(0xffffffffu, acc[e], off);
    if (lane == 0) {
#pragma unroll
        for (int e = 0; e < NE; e++) g_probs[(size_t)tok*NE + e] = acc[e];
    }
}

__global__ void router_post_kernel()
{
    int tok = blockIdx.x*blockDim.x + threadIdx.x;
    if (tok >= NTOK) return;
    float l[NE];
#pragma unroll
    for (int e = 0; e < NE; e++) l[e] = g_probs[(size_t)tok*NE + e];
    float mx = l[0];
#pragma unroll
    for (int e = 1; e < NE; e++) mx = fmaxf(mx, l[e]);
    float sum = 0.f;
#pragma unroll
    for (int e = 0; e < NE; e++) { l[e] = __expf(l[e]-mx); sum += l[e]; }
    float inv = 1.f/sum;
#pragma unroll
    for (int e = 0; e < NE; e++) { l[e] *= inv; g_probs[(size_t)tok*NE + e] = l[e]; }
    int b1 = 0; float p1 = l[0];
#pragma unroll
    for (int e = 1; e < NE; e++) if (l[e] > p1) { p1 = l[e]; b1 = e; }
    int b2 = -1; float p2 = -1.f;
#pragma unroll
    for (int e = 0; e < NE; e++) if (e != b1 && l[e] > p2) { p2 = l[e]; b2 = e; }
    if (b2 < 0) { b2 = (b1 + 1) & 7; p2 = l[b2]; }
    float s2 = p1 + p2;
    int pos1 = atomicAdd(&g_ecnt[b1], 1);
    g_elist[b1*NTOK + pos1] = tok; g_egate[b1*NTOK + pos1] = p1/s2;
    int pos2 = atomicAdd(&g_ecnt[b2], 1);
    g_elist[b2*NTOK + pos2] = tok; g_egate[b2*NTOK + pos2] = p2/s2;
}

__global__ void eoffp_kernel()
{
    if (threadIdx.x == 0) {
        int off = 0;
#pragma unroll
        for (int e = 0; e < NE; e++) {
            g_eoffp[e] = off;
            off += ((g_ecnt[e] + 127) / 128) * 128;
        }
        g_eoffp[NE] = off;
    }
}

// ---------------- aux loss (prob-sum reduction fused in; one block, 8 warps) ----------------
__global__ void aux_kernel(float* __restrict__ out, int out_size)
{
    if (out_size < NTOK*NC + 1) return;
    int tid = threadIdx.x, w = tid >> 5, lane = tid & 31;
    float s = 0.f;
    for (int t = lane; t < NTOK; t += 32) s += g_probs[(size_t)t*NE + w];
#pragma unroll
    for (int o = 16; o; o >>= 1) s += __shfl_xor_sync(0xffffffffu, s, o);
    __shared__ float ps[NE];
    if (lane == 0) ps[w] = s;
    __syncthreads();
    if (tid == 0) {
        float a = 0.f;
#pragma unroll
        for (int e = 0; e < NE; e++) {
            float f = (float)g_ecnt[e] / (float)(NTOK*2);
            a += f * (ps[e] / (float)NTOK);
        }
        out[(size_t)NTOK*NC] = (float)NE * a;
    }
}

// ---------------- launch ----------------
extern "C" void kernel_launch(void* const* d_in, const int* in_sizes, int n_in,
                              void* d_out, int out_size)
{
    const float* x    = (const float*)d_in[0];
    const float* cosp = (const float*)d_in[1];
    const float* sinp = (const float*)d_in[2];
    const float* ln1  = (const float*)d_in[3];
    const float* q_w  = (const float*)d_in[4];
    const float* k_w  = (const float*)d_in[5];
    const float* v_w  = (const float*)d_in[6];
    const float* o_w  = (const float*)d_in[7];
    const float* ln2  = (const float*)d_in[8];
    const float* rw   = (const float*)d_in[9];
    const float* W1   = (const float*)d_in[10];
    const float* W2   = (const float*)d_in[11];
    const float* W3   = (const float*)d_in[12];
    float* out = (float*)d_out;

    float *xn, *att;
    cudaGetSymbolAddress((void**)&xn,  g_xn);
    cudaGetSymbolAddress((void**)&att, g_att);

    const int ATT_SMSZ = (int)sizeof(AttnSmem);
    cudaFuncSetAttribute(attn_kernel, cudaFuncAttributeMaxDynamicSharedMemorySize, ATT_SMSZ);

    // 1) pre-attention norm
    rmsnorm_kernel<<<NTOK, 256>>>(x, ln1, xn);
    // 2) fused QKV projections
    qkv_gemm<<<dim3(NTOK/128, 12), 128>>>(xn, q_w, k_w, v_w);
    // 3) RoPE (q + k in one launch)
    rope_kernel<<<(ROPE_QTOT + ROPE_KTOT + 255)/256, 256>>>(cosp, sinp);
    // 4) tensor-core flash attention (best measured configuration)
    attn_kernel<<<dim3(NT/64, NB*NH), 256, ATT_SMSZ>>>();
    // 5) o-proj + residual
    oproj_gemm<<<dim3(NTOK/128, NC/128), 128>>>(att, o_w, out, x);
    // 6) pre-MoE norm
    rmsnorm_kernel<<<NTOK, 256>>>(out, ln2, xn);
    // 7) router
    router_logits_kernel<<<NTOK/4, 128>>>(xn, rw);
    router_post_kernel<<<NTOK/256, 256>>>();
    eoffp_kernel<<<1, 32>>>();
    // 8) experts — fused gate (W1+W2+silu), then gated down-proj scatter
    gatefused_gemm<<<dim3(NTOK/128, NF/64, NE), 128>>>(xn, W1, W2);
    down_gemm<<<dim3(NTOK/128, NC/128, NE), 128>>>(W3, out);
    // 9) aux loss (psum fused)
    aux_kernel<<<1, 256>>>(out, out_size);
}